// round 1
// baseline (speedup 1.0000x reference)
#include <cuda_runtime.h>
#include <math.h>
#include <stdint.h>

// Problem constants
#define NN   65536
#define CC   256
#define EE   458752
#define BB   8
#define EMBC 512
#define NET  7
#define NNT  7
#define KP   264      // padded K  (256 + 7 one-hot + 1 zero pad)
#define NC   1792     // 7 * 256
#define NGRP 32
#define CPG  8

// ---------------- device global scratch ----------------
__device__ float    g_xa[(size_t)NN * KP];        // 69 MB  (silu(gn) + one-hot, tf32-rounded)
__device__ float    g_Z [(size_t)NN * NC];        // 470 MB (per-node per-type GEMM output)
__device__ float    g_h2[(size_t)NN * CC];        // 67 MB  (conv1 out + emb)
__device__ float    g_Wcat[(size_t)KP * NC];      // 1.9 MB (padded, tf32-rounded weights)
__device__ float    g_emb_out[BB * CC];
__device__ float    g_S1[BB * NGRP], g_S2[BB * NGRP];
__device__ float    g_mu[BB * NGRP], g_istd[BB * NGRP];
__device__ int      g_cnt[BB];
__device__ int      g_deg[NN];
__device__ int      g_cursor[NN];
__device__ int      g_rowptr[NN + 1];
__device__ int      g_tmp[NN];
__device__ int      g_bsum[256];
__device__ int      g_boff[256];
__device__ unsigned g_edges[EE];                  // (col<<3)|type

// ---------------- helpers ----------------
__device__ __forceinline__ float tf32r(float x) {
    unsigned u;
    asm("cvt.rna.tf32.f32 %0, %1;" : "=r"(u) : "f"(x));
    return __uint_as_float(u);
}
__device__ __forceinline__ float silu(float x) {
    return x / (1.0f + expf(-x));
}
__device__ __forceinline__ void f4add(float4& a, const float4 b) {
    a.x += b.x; a.y += b.y; a.z += b.z; a.w += b.w;
}
__device__ __forceinline__ void mma_tf32(float* c, const unsigned* a, const unsigned* b) {
    asm volatile(
        "mma.sync.aligned.m16n8k8.row.col.f32.tf32.tf32.f32 "
        "{%0,%1,%2,%3}, {%4,%5,%6,%7}, {%8,%9}, {%0,%1,%2,%3};"
        : "+f"(c[0]), "+f"(c[1]), "+f"(c[2]), "+f"(c[3])
        : "r"(a[0]), "r"(a[1]), "r"(a[2]), "r"(a[3]), "r"(b[0]), "r"(b[1]));
}

// ---------------- setup / CSR kernels ----------------
__global__ void k_zero1() {
    int i = blockIdx.x * 256 + threadIdx.x;   // 65536 threads
    g_deg[i] = 0;
    g_cursor[i] = 0;
    if (i < BB) g_cnt[i] = 0;
    if (i < BB * NGRP) { g_S1[i] = 0.f; g_S2[i] = 0.f; }
}
__global__ void k_zero_stats() {
    int i = threadIdx.x;
    g_S1[i] = 0.f; g_S2[i] = 0.f;
}
__global__ void k_hist(const int* __restrict__ row) {
    int e = blockIdx.x * 256 + threadIdx.x;
    atomicAdd(&g_deg[row[e]], 1);
}
__global__ void k_scan1() {
    __shared__ int sh[256];
    int tid = threadIdx.x;
    int idx = blockIdx.x * 256 + tid;
    int v = g_deg[idx];
    sh[tid] = v; __syncthreads();
    for (int off = 1; off < 256; off <<= 1) {
        int t = (tid >= off) ? sh[tid - off] : 0;
        __syncthreads();
        sh[tid] += t;
        __syncthreads();
    }
    g_tmp[idx] = sh[tid];
    if (tid == 255) g_bsum[blockIdx.x] = sh[255];
}
__global__ void k_scan2() {
    __shared__ int sh[256];
    int tid = threadIdx.x;
    int v = g_bsum[tid];
    sh[tid] = v; __syncthreads();
    for (int off = 1; off < 256; off <<= 1) {
        int t = (tid >= off) ? sh[tid - off] : 0;
        __syncthreads();
        sh[tid] += t;
        __syncthreads();
    }
    g_boff[tid] = sh[tid] - v;   // exclusive block offset
}
__global__ void k_scan3() {
    int idx = blockIdx.x * 256 + threadIdx.x;
    g_rowptr[idx + 1] = g_tmp[idx] + g_boff[blockIdx.x];
    if (idx == 0) g_rowptr[0] = 0;
}
__global__ void k_fill(const int* __restrict__ row, const int* __restrict__ col,
                       const int* __restrict__ etype) {
    int e = blockIdx.x * 256 + threadIdx.x;
    int r = row[e];
    int pos = g_rowptr[r] + atomicAdd(&g_cursor[r], 1);
    g_edges[pos] = ((unsigned)col[e] << 3) | (unsigned)etype[e];
}
__global__ void k_count(const int* __restrict__ batch_id) {
    __shared__ int hc[BB];
    int tid = threadIdx.x;
    if (tid < BB) hc[tid] = 0;
    __syncthreads();
    int i = blockIdx.x * 256 + tid;
    atomicAdd(&hc[batch_id[i]], 1);
    __syncthreads();
    if (tid < BB) atomicAdd(&g_cnt[tid], hc[tid]);
}

// ---------------- emb path ----------------
__global__ void k_emb(const float* __restrict__ emb, const float* __restrict__ emb_w,
                      const float* __restrict__ emb_b) {
    int b = blockIdx.x, n = threadIdx.x;
    float acc = emb_b[n];
    for (int k = 0; k < EMBC; k++) {
        float e = emb[b * EMBC + k];
        acc += silu(e) * emb_w[k * CC + n];
    }
    g_emb_out[b * CC + n] = acc;
}

// ---------------- group norm ----------------
__device__ __forceinline__ void gn_flush(int b, float s1, float s2, int c) {
    #pragma unroll
    for (int off = 4; off >= 1; off >>= 1) {
        s1 += __shfl_down_sync(0xffffffffu, s1, off, 8);
        s2 += __shfl_down_sync(0xffffffffu, s2, off, 8);
    }
    if ((c & 7) == 0) {
        int g = c >> 3;
        atomicAdd(&g_S1[b * NGRP + g], s1);
        atomicAdd(&g_S2[b * NGRP + g], s2);
    }
}
__global__ void k_gn_stats(int useH2, const float* __restrict__ x,
                           const int* __restrict__ batch_id) {
    const float* data = useH2 ? g_h2 : x;
    __shared__ int s_bid[128];
    int c = threadIdx.x;
    int r0 = blockIdx.x * 128;
    if (c < 128) s_bid[c] = batch_id[r0 + c];
    __syncthreads();
    float s1 = 0.f, s2 = 0.f;
    int cur = s_bid[0];
    for (int j = 0; j < 128; j++) {
        int b = s_bid[j];
        if (b != cur) { gn_flush(cur, s1, s2, c); s1 = 0.f; s2 = 0.f; cur = b; }
        float v = data[(size_t)(r0 + j) * CC + c];
        s1 += v; s2 += v * v;
    }
    gn_flush(cur, s1, s2, c);
}
__global__ void k_gn_fin() {
    int tid = threadIdx.x;           // b*32+g
    int b = tid / NGRP;
    int n8 = g_cnt[b] * CPG;
    float D = (float)n8 + 1e-5f;
    float S1 = g_S1[tid], S2 = g_S2[tid];
    float mu = S1 / D;
    float var = (S2 - 2.f * mu * S1 + (float)n8 * mu * mu) / D;
    g_mu[tid] = mu;
    g_istd[tid] = rsqrtf(var + 1e-5f);
}
__global__ void k_gn_apply(int useH2, const float* __restrict__ x,
                           const int* __restrict__ batch_id,
                           const int* __restrict__ node_type,
                           const float* __restrict__ w, const float* __restrict__ bias) {
    const float* data = useH2 ? g_h2 : x;
    int i = blockIdx.x;
    int c = threadIdx.x;
    int b = batch_id[i];
    int g = c >> 3;
    float v = data[(size_t)i * CC + c];
    float y = (v - g_mu[b * NGRP + g]) * g_istd[b * NGRP + g] * w[c] + bias[c];
    g_xa[(size_t)i * KP + c] = tf32r(silu(y));
    if (c < 8) {
        float o = (c < NNT && node_type[i] == c) ? 1.0f : 0.0f;
        g_xa[(size_t)i * KP + CC + c] = o;   // one-hot + final zero pad
    }
}

// ---------------- weight prep ----------------
__global__ void k_prepW(const float* __restrict__ wsrc) {
    int idx = blockIdx.x * 256 + threadIdx.x;  // 264*1792 = 473088
    int k = idx / NC;
    int r = idx - k * NC;
    int t = r >> 8;
    int n = r & 255;
    float v = (k < 263) ? tf32r(wsrc[(size_t)(t * 263 + k) * CC + n]) : 0.0f;
    g_Wcat[idx] = v;
}

// ---------------- GEMM: g_Z[65536,1792] = g_xa[65536,264] @ g_Wcat[264,1792] --------
__global__ void __launch_bounds__(256, 2) k_gemm() {
    __shared__ float As[2][128][12];   // [buf][m][k] pad 8->12
    __shared__ float Bs[2][8][136];    // [buf][k][n] pad 128->136

    const int tid  = threadIdx.x;
    const int warp = tid >> 5, lane = tid & 31;
    const int wm = warp >> 1;          // 0..3  (m offset 32*wm)
    const int wn = warp & 1;           // 0..1  (n offset 64*wn)
    const int m0 = blockIdx.y * 128;
    const int n0 = blockIdx.x * 128;

    float acc[2][8][4];
    #pragma unroll
    for (int f = 0; f < 2; f++)
        #pragma unroll
        for (int j = 0; j < 8; j++)
            #pragma unroll
            for (int q = 0; q < 4; q++) acc[f][j][q] = 0.f;

    const int la_row = tid >> 1;          // 0..127
    const int la_k4  = (tid & 1) * 4;     // 0 or 4
    const int lb_row = tid >> 5;          // 0..7
    const int lb_c4  = (tid & 31) * 4;    // 0..124

    const float* Ag = g_xa + (size_t)(m0 + la_row) * KP + la_k4;
    const float* Bg = g_Wcat + (size_t)lb_row * NC + n0 + lb_c4;

    float4 ra = *(const float4*)(Ag);
    float4 rb = *(const float4*)(Bg);
    *(float4*)&As[0][la_row][la_k4] = ra;
    *(float4*)&Bs[0][lb_row][lb_c4] = rb;
    __syncthreads();

    const int arow = wm * 32 + (lane >> 2);
    const int kk = lane & 3;
    const int nn = wn * 64 + (lane >> 2);

    for (int s = 0; s < 33; s++) {
        int cur = s & 1;
        if (s < 32) {
            int k0 = (s + 1) * 8;
            ra = *(const float4*)(Ag + k0);
            rb = *(const float4*)(Bg + (size_t)k0 * NC);
        }
        unsigned af[2][4], bf[8][2];
        #pragma unroll
        for (int f = 0; f < 2; f++) {
            af[f][0] = __float_as_uint(As[cur][arow + f * 16][kk]);
            af[f][1] = __float_as_uint(As[cur][arow + f * 16 + 8][kk]);
            af[f][2] = __float_as_uint(As[cur][arow + f * 16][kk + 4]);
            af[f][3] = __float_as_uint(As[cur][arow + f * 16 + 8][kk + 4]);
        }
        #pragma unroll
        for (int j = 0; j < 8; j++) {
            bf[j][0] = __float_as_uint(Bs[cur][kk][nn + j * 8]);
            bf[j][1] = __float_as_uint(Bs[cur][kk + 4][nn + j * 8]);
        }
        #pragma unroll
        for (int f = 0; f < 2; f++)
            #pragma unroll
            for (int j = 0; j < 8; j++)
                mma_tf32(acc[f][j], af[f], bf[j]);

        if (s < 32) {
            *(float4*)&As[cur ^ 1][la_row][la_k4] = ra;
            *(float4*)&Bs[cur ^ 1][lb_row][lb_c4] = rb;
            __syncthreads();
        }
    }

    // epilogue
    const int rbase = m0 + wm * 32 + (lane >> 2);
    const int cb = n0 + wn * 64 + (lane & 3) * 2;
    #pragma unroll
    for (int f = 0; f < 2; f++) {
        int r = rbase + f * 16;
        #pragma unroll
        for (int j = 0; j < 8; j++) {
            int cc = cb + j * 8;
            *(float2*)&g_Z[(size_t)r * NC + cc]       = make_float2(acc[f][j][0], acc[f][j][1]);
            *(float2*)&g_Z[(size_t)(r + 8) * NC + cc] = make_float2(acc[f][j][2], acc[f][j][3]);
        }
    }
}

// ---------------- edge gather:  out[i] = sum_e Z[col_e, type_e]  (+emb / +skip) ------
__global__ void __launch_bounds__(256) k_gather(int mode, const int* __restrict__ batch_id,
                                                const float* __restrict__ skip,
                                                float* __restrict__ out_param) {
    int warp = threadIdx.x >> 5, lane = threadIdx.x & 31;
    int i = blockIdx.x * 8 + warp;
    int beg = g_rowptr[i], end = g_rowptr[i + 1];
    float4 a0 = make_float4(0.f, 0.f, 0.f, 0.f);
    float4 a1 = make_float4(0.f, 0.f, 0.f, 0.f);
    for (int e = beg; e < end; e++) {
        unsigned p = g_edges[e];
        int col = (int)(p >> 3);
        int t = (int)(p & 7);
        const float* zr = g_Z + (size_t)col * NC + t * CC;
        f4add(a0, *(const float4*)(zr + lane * 4));
        f4add(a1, *(const float4*)(zr + 128 + lane * 4));
    }
    if (mode == 1) {   // h2 = conv1 + emb_out[batch]
        int b = batch_id[i];
        const float* av = g_emb_out + b * CC;
        f4add(a0, *(const float4*)(av + lane * 4));
        f4add(a1, *(const float4*)(av + 128 + lane * 4));
        *(float4*)&g_h2[(size_t)i * CC + lane * 4] = a0;
        *(float4*)&g_h2[(size_t)i * CC + 128 + lane * 4] = a1;
    } else {           // out = x + conv2
        f4add(a0, *(const float4*)(skip + (size_t)i * CC + lane * 4));
        f4add(a1, *(const float4*)(skip + (size_t)i * CC + 128 + lane * 4));
        *(float4*)&out_param[(size_t)i * CC + lane * 4] = a0;
        *(float4*)&out_param[(size_t)i * CC + 128 + lane * 4] = a1;
    }
}

// ---------------- launch ----------------
extern "C" void kernel_launch(void* const* d_in, const int* in_sizes, int n_in,
                              void* d_out, int out_size) {
    const float* x        = (const float*)d_in[0];
    const float* emb      = (const float*)d_in[1];
    const int*   batch_id = (const int*)  d_in[2];
    const int*   ei       = (const int*)  d_in[3];   // [2,E]
    const int*   etype    = (const int*)  d_in[4];
    const int*   ntype    = (const int*)  d_in[5];
    const float* gn1_w    = (const float*)d_in[6];
    const float* gn1_b    = (const float*)d_in[7];
    const float* conv1_w  = (const float*)d_in[8];
    const float* emb_w    = (const float*)d_in[9];
    const float* emb_b    = (const float*)d_in[10];
    const float* gn2_w    = (const float*)d_in[11];
    const float* gn2_b    = (const float*)d_in[12];
    const float* conv2_w  = (const float*)d_in[13];
    float* out = (float*)d_out;

    const int* erow = ei;
    const int* ecol = ei + EE;

    // CSR build + init
    k_zero1<<<NN / 256, 256>>>();
    k_hist<<<EE / 256, 256>>>(erow);
    k_scan1<<<256, 256>>>();
    k_scan2<<<1, 256>>>();
    k_scan3<<<256, 256>>>();
    k_fill<<<EE / 256, 256>>>(erow, ecol, etype);
    k_count<<<NN / 256, 256>>>(batch_id);

    // emb path
    k_emb<<<BB, 256>>>(emb, emb_w, emb_b);

    // GN1 + silu -> xa
    k_gn_stats<<<NN / 128, 256>>>(0, x, batch_id);
    k_gn_fin<<<1, 256>>>();
    k_gn_apply<<<NN, 256>>>(0, x, batch_id, ntype, gn1_w, gn1_b);

    // conv1
    k_prepW<<<(KP * NC) / 256, 256>>>(conv1_w);
    k_gemm<<<dim3(NC / 128, NN / 128), 256>>>();
    k_gather<<<NN / 8, 256>>>(1, batch_id, nullptr, nullptr);

    // GN2 + silu -> xa
    k_zero_stats<<<1, 256>>>();
    k_gn_stats<<<NN / 128, 256>>>(1, x, batch_id);
    k_gn_fin<<<1, 256>>>();
    k_gn_apply<<<NN, 256>>>(1, x, batch_id, ntype, gn2_w, gn2_b);

    // conv2
    k_prepW<<<(KP * NC) / 256, 256>>>(conv2_w);
    k_gemm<<<dim3(NC / 128, NN / 128), 256>>>();
    k_gather<<<NN / 8, 256>>>(0, batch_id, x, out);
}

// round 4
// speedup vs baseline: 1.0147x; 1.0147x over previous
#include <cuda_runtime.h>
#include <math.h>
#include <stdint.h>

// Problem constants
#define NN   65536
#define CC   256
#define EE   458752
#define BB   8
#define EMBC 512
#define NET  7
#define NNT  7
#define NC   1792     // 7 * 256
#define NGRP 32
#define CPG  8

// ---------------- device global scratch ----------------
__device__ float    g_xa[(size_t)NN * CC];        // 67 MB  (silu(gn), tf32-rounded)
__device__ float    g_Z [(size_t)NN * NC];        // 470 MB (per-node per-type GEMM output)
__device__ float    g_h2[(size_t)NN * CC];        // 67 MB  (conv1 out + emb)
__device__ float    g_Wt[(size_t)NC * CC];        // 1.8 MB ([n][k], tf32-rounded)
__device__ float    g_Woh[NNT * NC];              // one-hot bias rows, exact fp32
__device__ float    g_emb_out[BB * CC];
__device__ float    g_S1[BB * NGRP], g_S2[BB * NGRP];
__device__ float    g_mu[BB * NGRP], g_istd[BB * NGRP];
__device__ int      g_cnt[BB];
__device__ int      g_deg[NN];
__device__ int      g_cursor[NN];
__device__ int      g_rowptr[NN + 1];
__device__ int      g_tmp[NN];
__device__ int      g_bsum[256];
__device__ int      g_boff[256];
__device__ unsigned g_edges[EE];                  // (col<<3)|type

// ---------------- helpers ----------------
__device__ __forceinline__ float tf32r(float x) {
    unsigned u;
    asm("cvt.rna.tf32.f32 %0, %1;" : "=r"(u) : "f"(x));
    return __uint_as_float(u);
}
__device__ __forceinline__ float silu(float x) { return x / (1.0f + expf(-x)); }
__device__ __forceinline__ void f4add(float4& a, const float4 b) {
    a.x += b.x; a.y += b.y; a.z += b.z; a.w += b.w;
}
__device__ __forceinline__ void mma_tf32(float* c, const unsigned* a, const unsigned* b) {
    asm volatile(
        "mma.sync.aligned.m16n8k8.row.col.f32.tf32.tf32.f32 "
        "{%0,%1,%2,%3}, {%4,%5,%6,%7}, {%8,%9}, {%0,%1,%2,%3};"
        : "+f"(c[0]), "+f"(c[1]), "+f"(c[2]), "+f"(c[3])
        : "r"(a[0]), "r"(a[1]), "r"(a[2]), "r"(a[3]), "r"(b[0]), "r"(b[1]));
}
__device__ __forceinline__ uint32_t smem_u32(const void* p) {
    uint32_t a;
    asm("{ .reg .u64 t; cvta.to.shared.u64 t, %1; cvt.u32.u64 %0, t; }" : "=r"(a) : "l"(p));
    return a;
}
#define CP_ASYNC16(dst, src) \
    asm volatile("cp.async.cg.shared.global [%0], [%1], 16;" :: "r"(dst), "l"(src))
#define CP_COMMIT() asm volatile("cp.async.commit_group;")
#define CP_WAIT(n)  asm volatile("cp.async.wait_group %0;" :: "n"(n))

// ---------------- setup / CSR kernels ----------------
__global__ void k_zero1() {
    int i = blockIdx.x * 256 + threadIdx.x;
    g_deg[i] = 0;
    g_cursor[i] = 0;
    if (i < BB) g_cnt[i] = 0;
    if (i < BB * NGRP) { g_S1[i] = 0.f; g_S2[i] = 0.f; }
}
__global__ void k_zero_stats() {
    int i = threadIdx.x;
    g_S1[i] = 0.f; g_S2[i] = 0.f;
}
__global__ void k_hist(const int* __restrict__ row) {
    int e = blockIdx.x * 256 + threadIdx.x;
    atomicAdd(&g_deg[row[e]], 1);
}
__global__ void k_scan1() {
    __shared__ int sh[256];
    int tid = threadIdx.x;
    int idx = blockIdx.x * 256 + tid;
    int v = g_deg[idx];
    sh[tid] = v; __syncthreads();
    for (int off = 1; off < 256; off <<= 1) {
        int t = (tid >= off) ? sh[tid - off] : 0;
        __syncthreads();
        sh[tid] += t;
        __syncthreads();
    }
    g_tmp[idx] = sh[tid];
    if (tid == 255) g_bsum[blockIdx.x] = sh[255];
}
__global__ void k_scan2() {
    __shared__ int sh[256];
    int tid = threadIdx.x;
    int v = g_bsum[tid];
    sh[tid] = v; __syncthreads();
    for (int off = 1; off < 256; off <<= 1) {
        int t = (tid >= off) ? sh[tid - off] : 0;
        __syncthreads();
        sh[tid] += t;
        __syncthreads();
    }
    g_boff[tid] = sh[tid] - v;
}
__global__ void k_scan3() {
    int idx = blockIdx.x * 256 + threadIdx.x;
    g_rowptr[idx + 1] = g_tmp[idx] + g_boff[blockIdx.x];
    if (idx == 0) g_rowptr[0] = 0;
}
__global__ void k_fill(const int* __restrict__ row, const int* __restrict__ col,
                       const int* __restrict__ etype) {
    int e = blockIdx.x * 256 + threadIdx.x;
    int r = row[e];
    int pos = g_rowptr[r] + atomicAdd(&g_cursor[r], 1);
    g_edges[pos] = ((unsigned)col[e] << 3) | (unsigned)etype[e];
}
__global__ void k_count(const int* __restrict__ batch_id) {
    __shared__ int hc[BB];
    int tid = threadIdx.x;
    if (tid < BB) hc[tid] = 0;
    __syncthreads();
    int i = blockIdx.x * 256 + tid;
    atomicAdd(&hc[batch_id[i]], 1);
    __syncthreads();
    if (tid < BB) atomicAdd(&g_cnt[tid], hc[tid]);
}

// ---------------- emb path ----------------
__global__ void k_emb(const float* __restrict__ emb, const float* __restrict__ emb_w,
                      const float* __restrict__ emb_b) {
    int b = blockIdx.x, n = threadIdx.x;
    float acc = emb_b[n];
    for (int k = 0; k < EMBC; k++) {
        float e = emb[b * EMBC + k];
        acc += silu(e) * emb_w[k * CC + n];
    }
    g_emb_out[b * CC + n] = acc;
}

// ---------------- group norm ----------------
__device__ __forceinline__ void gn_flush(int b, float s1, float s2, int c) {
    #pragma unroll
    for (int off = 4; off >= 1; off >>= 1) {
        s1 += __shfl_down_sync(0xffffffffu, s1, off, 8);
        s2 += __shfl_down_sync(0xffffffffu, s2, off, 8);
    }
    if ((c & 7) == 0) {
        int g = c >> 3;
        atomicAdd(&g_S1[b * NGRP + g], s1);
        atomicAdd(&g_S2[b * NGRP + g], s2);
    }
}
__global__ void k_gn_stats(int useH2, const float* __restrict__ x,
                           const int* __restrict__ batch_id) {
    const float* data = useH2 ? g_h2 : x;
    __shared__ int s_bid[128];
    int c = threadIdx.x;
    int r0 = blockIdx.x * 128;
    if (c < 128) s_bid[c] = batch_id[r0 + c];
    __syncthreads();
    float s1 = 0.f, s2 = 0.f;
    int cur = s_bid[0];
    for (int j = 0; j < 128; j++) {
        int b = s_bid[j];
        if (b != cur) { gn_flush(cur, s1, s2, c); s1 = 0.f; s2 = 0.f; cur = b; }
        float v = data[(size_t)(r0 + j) * CC + c];
        s1 += v; s2 += v * v;
    }
    gn_flush(cur, s1, s2, c);
}
__global__ void k_gn_fin() {
    int tid = threadIdx.x;
    int b = tid / NGRP;
    int n8 = g_cnt[b] * CPG;
    float D = (float)n8 + 1e-5f;
    float S1 = g_S1[tid], S2 = g_S2[tid];
    float mu = S1 / D;
    float var = (S2 - 2.f * mu * S1 + (float)n8 * mu * mu) / D;
    g_mu[tid] = mu;
    g_istd[tid] = rsqrtf(var + 1e-5f);
}
__global__ void k_gn_apply(int useH2, const float* __restrict__ x,
                           const int* __restrict__ batch_id,
                           const float* __restrict__ w, const float* __restrict__ bias) {
    const float* data = useH2 ? g_h2 : x;
    int i = blockIdx.x;
    int c = threadIdx.x;
    int b = batch_id[i];
    int g = c >> 3;
    float v = data[(size_t)i * CC + c];
    float y = (v - g_mu[b * NGRP + g]) * g_istd[b * NGRP + g] * w[c] + bias[c];
    g_xa[(size_t)i * CC + c] = tf32r(silu(y));
}

// ---------------- weight prep ----------------
// g_Wt[t*256+n][k] = W[(t*263+k)][n] (tf32-rounded), k<256
__global__ void k_prepW(const float* __restrict__ wsrc) {
    int idx = blockIdx.x * 256 + threadIdx.x;  // NC*256
    int r = idx >> 8;          // global n index 0..1791
    int k = idx & 255;
    int t = r >> 8;
    int n = r & 255;
    g_Wt[idx] = tf32r(wsrc[(size_t)(t * 263 + k) * CC + n]);
}
// g_Woh[j][t*256+n] = W[(t*263+256+j)][n]  (exact)
__global__ void k_prepOH(const float* __restrict__ wsrc) {
    int idx = blockIdx.x * 256 + threadIdx.x;  // NNT*NC = 12544
    if (idx >= NNT * NC) return;
    int j = idx / NC;
    int col = idx - j * NC;
    int t = col >> 8;
    int n = col & 255;
    g_Woh[idx] = wsrc[(size_t)(t * 263 + 256 + j) * CC + n];
}

// ---------------- GEMM: g_Z[65536,1792] = g_xa @ g_Wt^T + onehot bias ----------------
// CTA tile 128(m) x 256(n), BK=16, 8 warps (warp tile 64x64), 4-stage cp.async pipeline.
#define BKP   20          // padded K stride in smem (floats), conflict-free for frag reads
#define A_FL  (128 * BKP) // 2560
#define B_FL  (256 * BKP) // 5120
#define ST_FL (A_FL + B_FL)            // 7680 floats per stage
#define GSMEM (4 * ST_FL * 4)          // 122880 bytes

__device__ __forceinline__ void g2_load(uint32_t sbase, int s, int k0,
                                        const float* Ag, const float* Bg,
                                        int lr, int lk) {
    uint32_t st = sbase + (uint32_t)s * (ST_FL * 4);
    CP_ASYNC16(st + (uint32_t)(lr * BKP + lk) * 4,          Ag + k0);
    CP_ASYNC16(st + (uint32_t)((lr + 64) * BKP + lk) * 4,   Ag + (size_t)64 * CC + k0);
    uint32_t bt = st + A_FL * 4;
    #pragma unroll
    for (int i = 0; i < 4; i++)
        CP_ASYNC16(bt + (uint32_t)((lr + 64 * i) * BKP + lk) * 4,
                   Bg + (size_t)(64 * i) * CC + k0);
    CP_COMMIT();
}

__global__ void __launch_bounds__(256, 1) k_gemm2(const int* __restrict__ ntype) {
    extern __shared__ float sm[];
    const int tid  = threadIdx.x;
    const int warp = tid >> 5, lane = tid & 31;
    const int wm = warp & 1;            // m offset 64*wm
    const int wn = warp >> 1;           // n offset 64*wn
    const int m0 = blockIdx.y * 128;
    const int n0 = blockIdx.x * 256;
    const int lr = tid >> 2;            // 0..63
    const int lk = (tid & 3) * 4;       // 0,4,8,12
    const uint32_t sbase = smem_u32(sm);

    const float* Ag = g_xa + (size_t)(m0 + lr) * CC + lk;
    const float* Bg = g_Wt + (size_t)(n0 + lr) * CC + lk;

    float acc[4][8][4];
    #pragma unroll
    for (int mi = 0; mi < 4; mi++)
        #pragma unroll
        for (int ni = 0; ni < 8; ni++)
            #pragma unroll
            for (int q = 0; q < 4; q++) acc[mi][ni][q] = 0.f;

    g2_load(sbase, 0, 0,  Ag, Bg, lr, lk);
    g2_load(sbase, 1, 16, Ag, Bg, lr, lk);
    g2_load(sbase, 2, 32, Ag, Bg, lr, lk);

    const int r = lane >> 2, cq = lane & 3;

    #pragma unroll 1
    for (int s = 0; s < 16; s++) {
        CP_WAIT(2);
        __syncthreads();
        if (s + 3 < 16) g2_load(sbase, (s + 3) & 3, (s + 3) * 16, Ag, Bg, lr, lk);
        else            CP_COMMIT();

        const float* Asb = sm + (s & 3) * ST_FL;
        const float* Bsb = Asb + A_FL;

        #pragma unroll
        for (int kh = 0; kh < 2; kh++) {
            const int kb = kh * 8 + cq;
            unsigned af[4][4], bf[8][2];
            #pragma unroll
            for (int mi = 0; mi < 4; mi++) {
                const float* ap = Asb + (wm * 64 + mi * 16 + r) * BKP;
                af[mi][0] = __float_as_uint(ap[kb]);
                af[mi][1] = __float_as_uint(ap[8 * BKP + kb]);
                af[mi][2] = __float_as_uint(ap[kb + 4]);
                af[mi][3] = __float_as_uint(ap[8 * BKP + kb + 4]);
            }
            #pragma unroll
            for (int ni = 0; ni < 8; ni++) {
                const float* bp = Bsb + (wn * 64 + ni * 8 + r) * BKP;
                bf[ni][0] = __float_as_uint(bp[kb]);
                bf[ni][1] = __float_as_uint(bp[kb + 4]);
            }
            #pragma unroll
            for (int mi = 0; mi < 4; mi++)
                #pragma unroll
                for (int ni = 0; ni < 8; ni++)
                    mma_tf32(acc[mi][ni], af[mi], bf[ni]);
        }
    }

    // epilogue: + one-hot bias, store to g_Z
    const int c2 = (lane & 3) * 2;
    #pragma unroll
    for (int mi = 0; mi < 4; mi++) {
        int row = m0 + wm * 64 + mi * 16 + r;
        int nt0 = ntype[row], nt1 = ntype[row + 8];
        const float* oh0 = g_Woh + nt0 * NC + n0;
        const float* oh1 = g_Woh + nt1 * NC + n0;
        float* z0 = g_Z + (size_t)row * NC + n0;
        float* z1 = z0 + (size_t)8 * NC;
        #pragma unroll
        for (int ni = 0; ni < 8; ni++) {
            int col = wn * 64 + ni * 8 + c2;
            float2 b0 = *(const float2*)(oh0 + col);
            float2 b1 = *(const float2*)(oh1 + col);
            *(float2*)(z0 + col) = make_float2(acc[mi][ni][0] + b0.x, acc[mi][ni][1] + b0.y);
            *(float2*)(z1 + col) = make_float2(acc[mi][ni][2] + b1.x, acc[mi][ni][3] + b1.y);
        }
    }
}

// ---------------- edge gather:  out[i] = sum_e Z[col_e, type_e]  (+emb / +skip) ------
__global__ void __launch_bounds__(256) k_gather(int mode, const int* __restrict__ batch_id,
                                                const float* __restrict__ skip,
                                                float* __restrict__ out_param) {
    int warp = threadIdx.x >> 5, lane = threadIdx.x & 31;
    int i = blockIdx.x * 8 + warp;
    int beg = g_rowptr[i], end = g_rowptr[i + 1];
    float4 a0 = make_float4(0.f, 0.f, 0.f, 0.f);
    float4 a1 = make_float4(0.f, 0.f, 0.f, 0.f);
    for (int e = beg; e < end; e++) {
        unsigned p = g_edges[e];
        int col = (int)(p >> 3);
        int t = (int)(p & 7);
        const float* zr = g_Z + (size_t)col * NC + t * CC;
        f4add(a0, *(const float4*)(zr + lane * 4));
        f4add(a1, *(const float4*)(zr + 128 + lane * 4));
    }
    if (mode == 1) {   // h2 = conv1 + emb_out[batch]
        int b = batch_id[i];
        const float* av = g_emb_out + b * CC;
        f4add(a0, *(const float4*)(av + lane * 4));
        f4add(a1, *(const float4*)(av + 128 + lane * 4));
        *(float4*)&g_h2[(size_t)i * CC + lane * 4] = a0;
        *(float4*)&g_h2[(size_t)i * CC + 128 + lane * 4] = a1;
    } else {           // out = x + conv2
        f4add(a0, *(const float4*)(skip + (size_t)i * CC + lane * 4));
        f4add(a1, *(const float4*)(skip + (size_t)i * CC + 128 + lane * 4));
        *(float4*)&out_param[(size_t)i * CC + lane * 4] = a0;
        *(float4*)&out_param[(size_t)i * CC + 128 + lane * 4] = a1;
    }
}

// ---------------- launch ----------------
extern "C" void kernel_launch(void* const* d_in, const int* in_sizes, int n_in,
                              void* d_out, int out_size) {
    const float* x        = (const float*)d_in[0];
    const float* emb      = (const float*)d_in[1];
    const int*   batch_id = (const int*)  d_in[2];
    const int*   ei       = (const int*)  d_in[3];   // [2,E]
    const int*   etype    = (const int*)  d_in[4];
    const int*   ntype    = (const int*)  d_in[5];
    const float* gn1_w    = (const float*)d_in[6];
    const float* gn1_b    = (const float*)d_in[7];
    const float* conv1_w  = (const float*)d_in[8];
    const float* emb_w    = (const float*)d_in[9];
    const float* emb_b    = (const float*)d_in[10];
    const float* gn2_w    = (const float*)d_in[11];
    const float* gn2_b    = (const float*)d_in[12];
    const float* conv2_w  = (const float*)d_in[13];
    float* out = (float*)d_out;

    const int* erow = ei;
    const int* ecol = ei + EE;

    cudaFuncSetAttribute(k_gemm2, cudaFuncAttributeMaxDynamicSharedMemorySize, GSMEM);

    // CSR build + init
    k_zero1<<<NN / 256, 256>>>();
    k_hist<<<EE / 256, 256>>>(erow);
    k_scan1<<<256, 256>>>();
    k_scan2<<<1, 256>>>();
    k_scan3<<<256, 256>>>();
    k_fill<<<EE / 256, 256>>>(erow, ecol, etype);
    k_count<<<NN / 256, 256>>>(batch_id);

    // emb path
    k_emb<<<BB, 256>>>(emb, emb_w, emb_b);

    // GN1 + silu -> xa
    k_gn_stats<<<NN / 128, 256>>>(0, x, batch_id);
    k_gn_fin<<<1, 256>>>();
    k_gn_apply<<<NN, 256>>>(0, x, batch_id, gn1_w, gn1_b);

    // conv1
    k_prepW<<<(NC * CC) / 256, 256>>>(conv1_w);
    k_prepOH<<<(NNT * NC + 255) / 256, 256>>>(conv1_w);
    k_gemm2<<<dim3(NC / 256, NN / 128), 256, GSMEM>>>(ntype);
    k_gather<<<NN / 8, 256>>>(1, batch_id, nullptr, nullptr);

    // GN2 + silu -> xa
    k_zero_stats<<<1, 256>>>();
    k_gn_stats<<<NN / 128, 256>>>(1, x, batch_id);
    k_gn_fin<<<1, 256>>>();
    k_gn_apply<<<NN, 256>>>(1, x, batch_id, gn2_w, gn2_b);

    // conv2
    k_prepW<<<(NC * CC) / 256, 256>>>(conv2_w);
    k_prepOH<<<(NNT * NC + 255) / 256, 256>>>(conv2_w);
    k_gemm2<<<dim3(NC / 256, NN / 128), 256, GSMEM>>>(ntype);
    k_gather<<<NN / 8, 256>>>(0, batch_id, x, out);
}